// round 1
// baseline (speedup 1.0000x reference)
#include <cuda_runtime.h>
#include <cuda_bf16.h>

// Nadaraya-Watson kernel regression, single fused pass.
// queries: [N] f32, keys: [N,K] f32, values: [N,K] f32, w: [1] f32
// out[i] = sum_k exp(-0.5*((q_i-keys_ik)*w)^2) * values_ik / sum_k exp(...)
// Scores are <= 0 so exp in (0,1]; max-subtraction is numerically unnecessary
// for this data distribution -> single streaming pass over keys+values.

#define THREADS 256

__global__ void __launch_bounds__(THREADS, 8)
nw_regression_kernel(const float* __restrict__ q,
                     const float4* __restrict__ keys,
                     const float4* __restrict__ vals,
                     const float* __restrict__ w,
                     float* __restrict__ out,
                     int K4) {
    const int row = blockIdx.x;
    const float qi = q[row];
    const float wv = w[0];

    const float4* __restrict__ krow = keys + (size_t)row * K4;
    const float4* __restrict__ vrow = vals + (size_t)row * K4;

    float s = 0.0f;    // sum of exp
    float acc = 0.0f;  // sum of exp * value

    // K4 = 2048, THREADS = 256 -> 8 iterations; unroll for MLP.
    #pragma unroll 4
    for (int j = threadIdx.x; j < K4; j += THREADS) {
        float4 k4 = krow[j];
        float4 v4 = vrow[j];

        float d0 = (qi - k4.x) * wv;
        float d1 = (qi - k4.y) * wv;
        float d2 = (qi - k4.z) * wv;
        float d3 = (qi - k4.w) * wv;

        float e0 = __expf(-0.5f * d0 * d0);
        float e1 = __expf(-0.5f * d1 * d1);
        float e2 = __expf(-0.5f * d2 * d2);
        float e3 = __expf(-0.5f * d3 * d3);

        s   += (e0 + e1) + (e2 + e3);
        acc += (e0 * v4.x + e1 * v4.y) + (e2 * v4.z + e3 * v4.w);
    }

    // Warp reduction
    #pragma unroll
    for (int off = 16; off > 0; off >>= 1) {
        s   += __shfl_down_sync(0xFFFFFFFFu, s,   off);
        acc += __shfl_down_sync(0xFFFFFFFFu, acc, off);
    }

    // Cross-warp reduction via shared memory
    __shared__ float sh_s[THREADS / 32];
    __shared__ float sh_a[THREADS / 32];
    const int lane = threadIdx.x & 31;
    const int wid  = threadIdx.x >> 5;
    if (lane == 0) { sh_s[wid] = s; sh_a[wid] = acc; }
    __syncthreads();

    if (wid == 0) {
        s   = (lane < THREADS / 32) ? sh_s[lane] : 0.0f;
        acc = (lane < THREADS / 32) ? sh_a[lane] : 0.0f;
        #pragma unroll
        for (int off = 4; off > 0; off >>= 1) {
            s   += __shfl_down_sync(0xFFFFFFFFu, s,   off);
            acc += __shfl_down_sync(0xFFFFFFFFu, acc, off);
        }
        if (lane == 0) out[row] = acc / s;
    }
}

extern "C" void kernel_launch(void* const* d_in, const int* in_sizes, int n_in,
                              void* d_out, int out_size) {
    const float* q    = (const float*)d_in[0];   // [N]
    const float* keys = (const float*)d_in[1];   // [N,K]
    const float* vals = (const float*)d_in[2];   // [N,K]
    const float* w    = (const float*)d_in[3];   // [1]
    float* out = (float*)d_out;

    const int N = in_sizes[0];
    const int K = in_sizes[1] / N;
    const int K4 = K / 4;

    nw_regression_kernel<<<N, THREADS>>>(
        q, (const float4*)keys, (const float4*)vals, w, out, K4);
}